// round 12
// baseline (speedup 1.0000x reference)
#include <cuda_runtime.h>
#include <cuda_bf16.h>
#include <cstdint>

// ============================================================================
// IMMA (mma.sync m16n8k32 s8) implicit-GEMM conv stack, int8x2 split
// precision (per-tensor act scale, per-cout weight scale), s32 accumulate.
// Gmem activations: NHWC bf16 hi/lo planes (for pools + amax) AND NHWC int8
// hi/lo planes (conv operands, produced by a quantize pass).
// M-tile = 256 px (16x16), N-tile = 64, K chunked by 64, 256 threads,
// 3-stage cp.async pipeline.
// ============================================================================

#define BATCH 4
#define PL  37748736   // bf16 plane stride (elements)
#define QPL 37748736   // int8 plane stride (elements)
#define QMAX 16256.0f

__device__ __nv_bfloat16 g_actA[2 * PL];    // bf16 ping (also f32 NHWC scratch)
__device__ __nv_bfloat16 g_actB[2 * PL];    // bf16 pong
__device__ int8_t        g_qA[2 * QPL];     // int8 ping (hi|lo)
__device__ int8_t        g_qB[2 * QPL];     // int8 pong
__device__ int8_t        g_wq[15261696];    // per layer: [hi plane][lo plane]
__device__ float         g_wscale[2624];    // per-cout weight scales
__device__ float         g_amax[16];        // per-tensor activation absmax (zero-init)

// ---------------- PTX helpers (arch-neutral, sm_80-class) ----------------
static __device__ __forceinline__ uint32_t smem_u32(const void* p) {
    uint32_t a;
    asm("{ .reg .u64 t; cvta.to.shared.u64 t, %1; cvt.u32.u64 %0, t; }" : "=r"(a) : "l"(p));
    return a;
}
static __device__ __forceinline__ void cp16(uint32_t dst, const void* src, uint32_t sz) {
    asm volatile("cp.async.cg.shared.global [%0], [%1], 16, %2;"
                 :: "r"(dst), "l"(src), "r"(sz) : "memory");
}
#define CP_COMMIT() asm volatile("cp.async.commit_group;" ::: "memory")
#define CP_WAIT1()  asm volatile("cp.async.wait_group 1;" ::: "memory")
#define CP_WAIT0()  asm volatile("cp.async.wait_group 0;" ::: "memory")

#define LDSM_X4(r, addr) \
    asm volatile("ldmatrix.sync.aligned.m8n8.x4.shared.b16 {%0,%1,%2,%3}, [%4];" \
        : "=r"((r)[0]), "=r"((r)[1]), "=r"((r)[2]), "=r"((r)[3]) : "r"(addr))

#define IMMA16832(d, a, b) \
    asm volatile("mma.sync.aligned.m16n8k32.row.col.s32.s8.s8.s32 " \
        "{%0,%1,%2,%3}, {%4,%5,%6,%7}, {%8,%9}, {%0,%1,%2,%3};" \
        : "+r"((d)[0]), "+r"((d)[1]), "+r"((d)[2]), "+r"((d)[3]) \
        : "r"((a)[0]), "r"((a)[1]), "r"((a)[2]), "r"((a)[3]), "r"((b)[0]), "r"((b)[1]))

static __device__ __forceinline__ void blockAtomicMaxF(float v, float* dst,
                                                       float* sred, int lane, int wid) {
    #pragma unroll
    for (int o = 16; o > 0; o >>= 1)
        v = fmaxf(v, __shfl_xor_sync(0xffffffffu, v, o));
    if (lane == 0) sred[wid] = v;
    __syncthreads();
    if (wid == 0 && lane == 0) {
        float m = sred[0];
        #pragma unroll
        for (int i = 1; i < 8; i++) m = fmaxf(m, sred[i]);
        atomicMax((int*)dst, __float_as_int(m));
    }
}

// ============================================================================
// conv IMMA kernel. M=256 px (16x16), NT=64, K64 chunks, 8 warps = 4m x 2n.
// smem rows = 64B (one K64 int8 slice, one plane). 3 stages.
// ============================================================================
__global__ __launch_bounds__(256, 1)
void conv_imma(const int8_t* __restrict__ aHi, const int8_t* __restrict__ aLo,
               const int8_t* __restrict__ wHi, const int8_t* __restrict__ wLo,
               const float* __restrict__ wscale, const float* __restrict__ biasp,
               const float* __restrict__ amaxIn, float* amaxOut,
               const int* __restrict__ mask,
               __nv_bfloat16* __restrict__ oHi, __nv_bfloat16* __restrict__ oLo,
               float* __restrict__ oF32,
               int Cin, int Cout, int H, int W)
{
    extern __shared__ char smem[];
    constexpr int ASZ = 256 * 64;          // one A plane
    constexpr int BSZ = 64 * 64;           // one B plane
    constexpr int BUF = 2 * ASZ + 2 * BSZ; // 40960

    const int tid = threadIdx.x, lane = tid & 31, wid = tid >> 5;
    const int nB = Cout / 64;
    const int b  = blockIdx.z / nB, n0 = (blockIdx.z % nB) * 64;
    const int x0 = blockIdx.x * 16, y0 = blockIdx.y * 16;
    const int K  = 9 * Cin, NC = K / 64;

    // A staging: one pixel per thread, both planes (4+4 cp16)
    const int ay = y0 + (tid >> 4), ax = x0 + (tid & 15);
    int dil = 1;
    if (mask) dil += mask[(b * (H >> 1) + (ay >> 1)) * (W >> 1) + (ax >> 1)];
    const uint32_t xsA = (uint32_t)(((tid & 7) << 3) & 48);

    // B staging: 2 cp16 per thread (row bn, plane bpl, quad pair bq)
    const int bn = tid & 63, bpl = (tid >> 6) & 1, bq = tid >> 7;
    const int8_t* wPl = bpl ? wLo : wHi;
    const uint32_t xsB = (uint32_t)(((bn & 7) << 3) & 48);

    const uint32_t sbase = smem_u32(smem);
    int scb = 0, skx = 0, sky = 0, skb = 0;

    auto stage = [&](int q) {
        const uint32_t buf = sbase + q * BUF;
        const int yy = ay + (sky - 1) * dil, xx = ax + (skx - 1) * dil;
        const bool ib = (yy >= 0 && yy < H && xx >= 0 && xx < W);
        const size_t off = ((size_t)(b * H + (ib ? yy : 0)) * W + (ib ? xx : 0)) * Cin + scb;
        const uint32_t sz = ib ? 16u : 0u;
        const uint32_t dA = buf + (uint32_t)tid * 64;
        #pragma unroll
        for (int j = 0; j < 4; j++)
            cp16(dA + ((j * 16) ^ xsA), (const char*)(aHi + off) + j * 16, sz);
        #pragma unroll
        for (int j = 0; j < 4; j++)
            cp16(dA + ASZ + ((j * 16) ^ xsA), (const char*)(aLo + off) + j * 16, sz);
        {
            const char* srcB = (const char*)(wPl + (size_t)(n0 + bn) * K + skb) + bq * 32;
            const uint32_t dB = buf + 2 * ASZ + bpl * BSZ + (uint32_t)bn * 64;
            #pragma unroll
            for (int j = 0; j < 2; j++)
                cp16(dB + (((bq * 32) + j * 16) ^ xsB), srcB + j * 16, 16u);
        }
        CP_COMMIT();
        skb += 64; scb += 64;
        if (scb == Cin) { scb = 0; skx++; if (skx == 3) { skx = 0; sky++; } }
    };

    // MMA geometry: wm 0..3 (64 rows), wn 0..1 (32 cols)
    const int wm = wid >> 1, wn = wid & 1;
    const uint32_t xr = (uint32_t)(((lane & 7) << 3) & 48);
    uint32_t aRow[4], bRow[2];
    #pragma unroll
    for (int mt = 0; mt < 4; mt++)
        aRow[mt] = (uint32_t)(wm * 64 + mt * 16 + (lane & 15)) * 64;
    #pragma unroll
    for (int pr = 0; pr < 2; pr++)
        bRow[pr] = (uint32_t)(wn * 32 + pr * 16 + (lane & 7) + ((lane & 16) >> 1)) * 64;

    int accH[4][4][4], accM[4][4][4];
    #pragma unroll
    for (int mt = 0; mt < 4; mt++)
        #pragma unroll
        for (int nt = 0; nt < 4; nt++)
            #pragma unroll
            for (int e = 0; e < 4; e++) { accH[mt][nt][e] = 0; accM[mt][nt][e] = 0; }

    stage(0);
    stage(1);

    for (int c = 0; c < NC; c++) {
        if (c + 1 < NC) CP_WAIT1(); else CP_WAIT0();
        __syncthreads();
        if (c + 2 < NC) stage((c + 2) % 3);

        const uint32_t bA = sbase + (c % 3) * BUF;
        const uint32_t bB = bA + 2 * ASZ;

        #pragma unroll
        for (int s = 0; s < 2; s++) {
            const uint32_t cbA = (uint32_t)(s * 32) + (lane & 16);
            const uint32_t cbB = (uint32_t)(s * 32) + ((lane & 8) << 1);
            uint32_t bh[4][2], bl[4][2];
            #pragma unroll
            for (int pr = 0; pr < 2; pr++) {
                uint32_t t[4];
                LDSM_X4(t, bB + bRow[pr] + (cbB ^ xr));
                bh[2 * pr][0] = t[0]; bh[2 * pr][1] = t[1];
                bh[2 * pr + 1][0] = t[2]; bh[2 * pr + 1][1] = t[3];
                LDSM_X4(t, bB + BSZ + bRow[pr] + (cbB ^ xr));
                bl[2 * pr][0] = t[0]; bl[2 * pr][1] = t[1];
                bl[2 * pr + 1][0] = t[2]; bl[2 * pr + 1][1] = t[3];
            }
            #pragma unroll
            for (int mt = 0; mt < 4; mt++) {
                uint32_t ah[4], al[4];
                LDSM_X4(ah, bA + aRow[mt] + (cbA ^ xr));
                #pragma unroll
                for (int nt = 0; nt < 4; nt++) IMMA16832(accH[mt][nt], ah, bh[nt]);
                #pragma unroll
                for (int nt = 0; nt < 4; nt++) IMMA16832(accM[mt][nt], ah, bl[nt]);
                LDSM_X4(al, bA + ASZ + aRow[mt] + (cbA ^ xr));
                #pragma unroll
                for (int nt = 0; nt < 4; nt++) IMMA16832(accM[mt][nt], al, bh[nt]);
            }
        }
    }

    // ---- epilogue: dequant + bias + ReLU; bf16 planes (or fp32 NHWC) ----
    const float saf = amaxIn[0] * (1.0f / (QMAX * QMAX));  // sa*sb share /QMAX^2
    float tmax = 0.f;
    #pragma unroll
    for (int nt = 0; nt < 4; nt++) {
        const int ncol = n0 + wn * 32 + nt * 8 + 2 * (lane & 3);
        const float sc0 = saf * __ldg(wscale + ncol);
        const float sc1 = saf * __ldg(wscale + ncol + 1);
        const float b0v = __ldg(biasp + ncol);
        const float b1v = __ldg(biasp + ncol + 1);
        #pragma unroll
        for (int mt = 0; mt < 4; mt++) {
            #pragma unroll
            for (int rh = 0; rh < 2; rh++) {
                const int p = wm * 64 + mt * 16 + (lane >> 2) + rh * 8;
                const int y = y0 + (p >> 4), x = x0 + (p & 15);
                const size_t idx = ((size_t)(b * H + y) * W + x) * Cout + ncol;
                float v0 = fmaxf(fmaf(16384.f, (float)accH[mt][nt][2 * rh],
                                      128.f * (float)accM[mt][nt][2 * rh]) * sc0 + b0v, 0.f);
                float v1 = fmaxf(fmaf(16384.f, (float)accH[mt][nt][2 * rh + 1],
                                      128.f * (float)accM[mt][nt][2 * rh + 1]) * sc1 + b1v, 0.f);
                tmax = fmaxf(tmax, fmaxf(v0, v1));
                if (oF32) {
                    *(float2*)(oF32 + idx) = make_float2(v0, v1);
                } else {
                    __nv_bfloat16 h0 = __float2bfloat16(v0);
                    __nv_bfloat16 h1 = __float2bfloat16(v1);
                    __nv_bfloat16 l0 = __float2bfloat16(v0 - __bfloat162float(h0));
                    __nv_bfloat16 l1 = __float2bfloat16(v1 - __bfloat162float(h1));
                    *(__nv_bfloat162*)(oHi + idx) = __nv_bfloat162(h0, h1);
                    *(__nv_bfloat162*)(oLo + idx) = __nv_bfloat162(l0, l1);
                }
            }
        }
    }
    if (amaxOut) {
        __syncthreads();
        blockAtomicMaxF(tmax, amaxOut, (float*)smem, lane, wid);
    }
}

// ============================================================================
// Layer 1 (3->64, 384x384): FFMA2 direct conv -> bf16 planes + amax
// ============================================================================
__device__ __forceinline__ uint64_t pack2(float v) {
    uint64_t r; uint32_t u = __float_as_uint(v);
    asm("mov.b64 %0, {%1, %1};" : "=l"(r) : "r"(u));
    return r;
}
__device__ __forceinline__ void fma2(uint64_t& d, uint64_t a, uint64_t b) {
    asm("fma.rn.f32x2 %0, %1, %2, %0;" : "+l"(d) : "l"(a), "l"(b));
}

__global__ __launch_bounds__(256)
void conv1_pack_kernel(const float* __restrict__ in, const float* __restrict__ w,
                       const float* __restrict__ bias,
                       __nv_bfloat16* __restrict__ outHi, __nv_bfloat16* __restrict__ outLo,
                       float* amaxOut)
{
    __shared__ float s_in[3][18][18];
    __shared__ __align__(16) float s_w[27][64];
    __shared__ float s_b[64];
    __shared__ float s_red[8];
    const int b  = blockIdx.z;
    const int x0 = blockIdx.x * 16, y0 = blockIdx.y * 16;
    const int tid = threadIdx.x;

    for (int i = tid; i < 3 * 18 * 18; i += 256) {
        int ci = i / 324, r = (i % 324) / 18, cc = i % 18;
        int gy = y0 + r - 1, gx = x0 + cc - 1;
        float v = 0.f;
        if ((unsigned)gy < 384u && (unsigned)gx < 384u)
            v = in[((b * 3 + ci) * 384 + gy) * 384 + gx];
        (&s_in[0][0][0])[i] = v;
    }
    for (int i = tid; i < 27 * 64; i += 256) {
        int co = i & 63, t = i >> 6;
        int ci = t / 9, tap = t % 9;
        s_w[t][co] = w[(co * 3 + ci) * 9 + tap];
    }
    if (tid < 64) s_b[tid] = bias[tid];
    __syncthreads();

    const int px = tid & 15, py = tid >> 4;
    uint64_t a2[32];
    #pragma unroll
    for (int k = 0; k < 32; k++) a2[k] = 0ull;
    #pragma unroll
    for (int t = 0; t < 27; t++) {
        int ci = t / 9, tap = t % 9;
        uint64_t vv = pack2(s_in[ci][py + tap / 3][px + tap % 3]);
        const ulonglong2* wp = (const ulonglong2*)&s_w[t][0];
        #pragma unroll
        for (int k = 0; k < 16; k++) {
            ulonglong2 wv = wp[k];
            fma2(a2[2 * k],     vv, wv.x);
            fma2(a2[2 * k + 1], vv, wv.y);
        }
    }
    const size_t pix = (size_t)((b * 384 + y0 + py) * 384 + x0 + px);
    uint32_t ph[32], pll[32];
    float cmax = 0.f;
    #pragma unroll
    for (int j = 0; j < 32; j++) {
        float v0 = fmaxf(__uint_as_float((uint32_t)a2[j]) + s_b[2 * j], 0.f);
        float v1 = fmaxf(__uint_as_float((uint32_t)(a2[j] >> 32)) + s_b[2 * j + 1], 0.f);
        cmax = fmaxf(cmax, fmaxf(v0, v1));
        __nv_bfloat16 h0 = __float2bfloat16(v0), h1 = __float2bfloat16(v1);
        __nv_bfloat16 l0 = __float2bfloat16(v0 - __bfloat162float(h0));
        __nv_bfloat16 l1 = __float2bfloat16(v1 - __bfloat162float(h1));
        ph[j]  = ((uint32_t)__bfloat16_as_ushort(h1) << 16) | __bfloat16_as_ushort(h0);
        pll[j] = ((uint32_t)__bfloat16_as_ushort(l1) << 16) | __bfloat16_as_ushort(l0);
    }
    uint4* dH = (uint4*)(outHi + pix * 64);
    uint4* dL = (uint4*)(outLo + pix * 64);
    #pragma unroll
    for (int j = 0; j < 8; j++) {
        dH[j] = make_uint4(ph[4 * j], ph[4 * j + 1], ph[4 * j + 2], ph[4 * j + 3]);
        dL[j] = make_uint4(pll[4 * j], pll[4 * j + 1], pll[4 * j + 2], pll[4 * j + 3]);
    }
    __syncthreads();
    blockAtomicMaxF(cmax, amaxOut, s_red, tid & 31, tid >> 5);
}

// ============================================================================
// Quantize: bf16 hi/lo planes -> int8 hi/lo planes (per-tensor scale)
// ============================================================================
__global__ void quant_act(const __nv_bfloat16* __restrict__ inH,
                          const __nv_bfloat16* __restrict__ inL,
                          const float* __restrict__ amax,
                          int8_t* __restrict__ outH, int8_t* __restrict__ outL, int n4)
{
    int i = blockIdx.x * blockDim.x + threadIdx.x;
    if (i >= n4) return;
    const float am = amax[0];
    const float s = (am > 1e-20f) ? (QMAX / am) : 0.f;
    uint2 h2 = ((const uint2*)inH)[i];
    uint2 l2 = ((const uint2*)inL)[i];
    char4 qh, ql;
    #pragma unroll
    for (int e = 0; e < 4; e++) {
        uint32_t hw = (e < 2) ? h2.x : h2.y;
        uint32_t lw = (e < 2) ? l2.x : l2.y;
        int sh = (e & 1) * 16;
        float v = __bfloat162float(__ushort_as_bfloat16((unsigned short)((hw >> sh) & 0xffff)))
                + __bfloat162float(__ushort_as_bfloat16((unsigned short)((lw >> sh) & 0xffff)));
        int X = min((int)lrintf(v * s), 16256);
        int Xh = (X + 64) >> 7;
        int Xl = X - (Xh << 7);
        ((int8_t*)&qh)[e] = (int8_t)Xh;
        ((int8_t*)&ql)[e] = (int8_t)Xl;
    }
    ((char4*)outH)[i] = qh;
    ((char4*)outL)[i] = ql;
}

// ============================================================================
// Weight quantize: fp32 [cout][cin][3][3] -> int8 hi/lo, k = tap*Cin+ci,
// per-cout scale. One block per cout row.
// ============================================================================
__global__ void wquant_kernel(const float* __restrict__ w, int8_t* __restrict__ hi,
                              int8_t* __restrict__ lo, float* __restrict__ wscale, int Cin)
{
    __shared__ float sred[256];
    const int co = blockIdx.x, tid = threadIdx.x;
    const int K = Cin * 9;
    float am = 0.f;
    for (int k = tid; k < K; k += 256) am = fmaxf(am, fabsf(w[co * K + k]));
    sred[tid] = am;
    __syncthreads();
    for (int o = 128; o > 0; o >>= 1) {
        if (tid < o) sred[tid] = fmaxf(sred[tid], sred[tid + o]);
        __syncthreads();
    }
    am = sred[0];
    const float s = (am > 1e-20f) ? (QMAX / am) : 0.f;
    if (tid == 0) wscale[co] = (am > 1e-20f) ? (am / QMAX) * QMAX : 0.f;  // = am
    for (int k = tid; k < K; k += 256) {
        int ci = k / 9, tap = k - ci * 9;
        float v = w[co * K + k];
        int W = (int)lrintf(v * s);
        W = max(min(W, 16256), -16256);
        int Wh = (W >= 0) ? ((W + 64) >> 7) : -((-W + 64) >> 7);
        int Wl = W - (Wh << 7);
        int o = co * K + tap * Cin + ci;
        hi[o] = (int8_t)Wh;
        lo[o] = (int8_t)Wl;
    }
}

// ============================================================================
// Pools on bf16 hi/lo planes (unchanged)
// ============================================================================
static __device__ __forceinline__ float rec(const __nv_bfloat16* h, const __nv_bfloat16* l, size_t i) {
    return __bfloat162float(h[i]) + __bfloat162float(l[i]);
}

__global__ void maxpool2_pl(const __nv_bfloat16* __restrict__ inH, const __nv_bfloat16* __restrict__ inL,
                            __nv_bfloat16* __restrict__ outH, __nv_bfloat16* __restrict__ outL,
                            int C, int Ho, int Wo, int total)
{
    int i = blockIdx.x * blockDim.x + threadIdx.x;
    if (i >= total) return;
    int c = i % C; int t = i / C;
    int xo = t % Wo; t /= Wo;
    int yo = t % Ho; int b = t / Ho;
    int Wi = Wo * 2;
    size_t base = (size_t)((b * Ho * 2 + yo * 2) * Wi + xo * 2) * C + c;
    size_t o0 = base, o1 = base + C, o2 = base + (size_t)Wi * C, o3 = o2 + C;
    size_t best = o0; float bf = rec(inH, inL, o0);
    float f;
    f = rec(inH, inL, o1); if (f > bf) { bf = f; best = o1; }
    f = rec(inH, inL, o2); if (f > bf) { bf = f; best = o2; }
    f = rec(inH, inL, o3); if (f > bf) { bf = f; best = o3; }
    outH[i] = inH[best]; outL[i] = inL[best];
}

__global__ void irrpool_pl(const __nv_bfloat16* __restrict__ inH, const __nv_bfloat16* __restrict__ inL,
                           const int* __restrict__ mask,
                           __nv_bfloat16* __restrict__ outH, __nv_bfloat16* __restrict__ outL,
                           int C, int total)
{
    int i = blockIdx.x * blockDim.x + threadIdx.x;
    if (i >= total) return;
    int c = i % C; int t = i / C;
    int bx = t % 48; t /= 48;
    int by = t % 48; int b = t / 48;
    int m = mask[(b * 48 + by) * 48 + bx];
    size_t base = (size_t)((b * 96 + by * 2) * 96 + bx * 2) * C + c;
    size_t o[4] = { base, base + C, base + (size_t)96 * C, base + (size_t)96 * C + C };
    if (m) {
        size_t best = o[0]; float bf = rec(inH, inL, o[0]);
        #pragma unroll
        for (int j = 1; j < 4; j++) {
            float f = rec(inH, inL, o[j]);
            if (f > bf) { bf = f; best = o[j]; }
        }
        __nv_bfloat16 vh = inH[best], vl = inL[best];
        #pragma unroll
        for (int j = 0; j < 4; j++) { outH[o[j]] = vh; outL[o[j]] = vl; }
    } else {
        #pragma unroll
        for (int j = 0; j < 4; j++) { outH[o[j]] = inH[o[j]]; outL[o[j]] = inL[o[j]]; }
    }
}

// NHWC fp32 [4,96,96,512] -> NCHW fp32
__global__ void nhwc2nchw(const float* __restrict__ in, float* __restrict__ out)
{
    __shared__ float t[32][33];
    const int b = blockIdx.z;
    const int p0 = blockIdx.x * 32, c0 = blockIdx.y * 32;
    const int tx = threadIdx.x, ty = threadIdx.y;
    #pragma unroll
    for (int j = 0; j < 4; j++) {
        int row = ty * 4 + j;
        t[row][tx] = in[((size_t)b * 9216 + p0 + row) * 512 + c0 + tx];
    }
    __syncthreads();
    #pragma unroll
    for (int j = 0; j < 4; j++) {
        int row = ty * 4 + j;
        out[((size_t)b * 512 + c0 + row) * 9216 + p0 + tx] = t[tx][row];
    }
}

// ============================================================================
extern "C" void kernel_launch(void* const* d_in, const int* in_sizes, int n_in,
                              void* d_out, int out_size)
{
    (void)in_sizes; (void)n_in; (void)out_size;
    const float* batch = (const float*)d_in[0];
    const int*   mask  = (const int*)d_in[1];
    const float* Wt[10];
    const float* Bs[10];
    for (int i = 0; i < 10; i++) {
        Wt[i] = (const float*)d_in[2 + 2 * i];
        Bs[i] = (const float*)d_in[3 + 2 * i];
    }

    __nv_bfloat16 *A, *B;
    int8_t *qA, *qB, *WQ;
    float *WS, *AM;
    cudaGetSymbolAddress((void**)&A,  g_actA);
    cudaGetSymbolAddress((void**)&B,  g_actB);
    cudaGetSymbolAddress((void**)&qA, g_qA);
    cudaGetSymbolAddress((void**)&qB, g_qB);
    cudaGetSymbolAddress((void**)&WQ, g_wq);
    cudaGetSymbolAddress((void**)&WS, g_wscale);
    cudaGetSymbolAddress((void**)&AM, g_amax);
    float* O = (float*)d_out;

    static const int    cins[9]  = {64, 64, 128, 128, 256, 256, 256, 512, 512};
    static const int    couts[9] = {64, 128, 128, 256, 256, 256, 512, 512, 512};
    static const size_t offs[9]  = {0, 73728, 221184, 516096, 1105920,
                                    2285568, 3465216, 5824512, 10543104};
    static const int    wsoff[9] = {0, 64, 192, 320, 576, 832, 1088, 1600, 2112};

    for (int l = 0; l < 9; l++)
        wquant_kernel<<<couts[l], 256>>>(Wt[l + 1], WQ + offs[l],
            WQ + offs[l] + (size_t)couts[l] * cins[l] * 9, WS + wsoff[l], cins[l]);

    conv1_pack_kernel<<<dim3(24, 24, BATCH), 256>>>(batch, Wt[0], Bs[0], A, A + PL, AM + 0);

    cudaFuncSetAttribute(conv_imma, cudaFuncAttributeMaxDynamicSharedMemorySize, 122880);

    auto quant = [&](const __nv_bfloat16* in, const float* am, int8_t* out, int n) {
        int n4 = n / 4;
        quant_act<<<(n4 + 255) / 256, 256>>>(in, in + PL, am, out, out + QPL, n4);
    };
    auto imma = [&](const int8_t* in, int l, const float* bias, const int* mk,
                    const float* amIn, float* amOut,
                    __nv_bfloat16* outPl, float* oF, int H) {
        int Cin = cins[l], Cout = couts[l];
        dim3 g(H / 16, H / 16, BATCH * (Cout / 64));
        conv_imma<<<g, 256, 122880>>>(in, in + QPL,
            WQ + offs[l], WQ + offs[l] + (size_t)Cout * Cin * 9,
            WS + wsoff[l], bias, amIn, amOut, mk,
            outPl, outPl ? outPl + PL : nullptr, oF, Cin, Cout, H, H);
    };

    quant(A, AM + 0, qA, BATCH * 384 * 384 * 64);
    imma(qA, 0, Bs[1], nullptr, AM + 0, AM + 1, B, nullptr, 384);         // L2
    { int tot = BATCH * 192 * 192 * 64;
      maxpool2_pl<<<(tot + 255) / 256, 256>>>(B, B + PL, A, A + PL, 64, 192, 192, tot); }
    quant(A, AM + 1, qA, BATCH * 192 * 192 * 64);
    imma(qA, 1, Bs[2], nullptr, AM + 1, AM + 2, B, nullptr, 192);         // L3
    quant(B, AM + 2, qB, BATCH * 192 * 192 * 128);
    imma(qB, 2, Bs[3], nullptr, AM + 2, AM + 3, A, nullptr, 192);         // L4
    { int tot = BATCH * 96 * 96 * 128;
      maxpool2_pl<<<(tot + 255) / 256, 256>>>(A, A + PL, B, B + PL, 128, 96, 96, tot); }
    quant(B, AM + 3, qB, BATCH * 96 * 96 * 128);
    imma(qB, 3, Bs[4], nullptr, AM + 3, AM + 4, A, nullptr, 96);          // L5
    quant(A, AM + 4, qA, BATCH * 96 * 96 * 256);
    imma(qA, 4, Bs[5], nullptr, AM + 4, AM + 5, B, nullptr, 96);          // L6
    quant(B, AM + 5, qB, BATCH * 96 * 96 * 256);
    imma(qB, 5, Bs[6], nullptr, AM + 5, AM + 6, A, nullptr, 96);          // L7
    { int tot = BATCH * 48 * 48 * 256;
      irrpool_pl<<<(tot + 255) / 256, 256>>>(A, A + PL, mask, B, B + PL, 256, tot); }
    quant(B, AM + 6, qB, BATCH * 96 * 96 * 256);
    imma(qB, 6, Bs[7], mask, AM + 6, AM + 7, A, nullptr, 96);             // L8
    quant(A, AM + 7, qA, BATCH * 96 * 96 * 512);
    imma(qA, 7, Bs[8], mask, AM + 7, AM + 8, B, nullptr, 96);             // L9
    quant(B, AM + 8, qB, BATCH * 96 * 96 * 512);
    float* fA = (float*)A;
    imma(qB, 8, Bs[9], mask, AM + 8, nullptr, nullptr, fA, 96);           // L10
    nhwc2nchw<<<dim3(288, 16, 4), dim3(32, 8)>>>(fA, O);
}